// round 9
// baseline (speedup 1.0000x reference)
#include <cuda_runtime.h>

// Problem constants (fixed by setup_inputs)
#define BATCH 4
#define N_UP  8192
#define N_GT  8192
#define N_RAD 1024
#define RCHUNK 256         // radar pass: b-points per block tile
#define NTHREADS 256
#define NRED 64            // partial-reduce blocks

// Running min of squared distance per point, stored as sign-flipped float bits:
//   key = __float_as_int(d) ^ 0x80000000   (d >= 0)
// Keys are negative ints, monotone increasing in d, so zero-initialized state
// (signed 0 > any key) acts as +infinity. reduce_partial resets slots to 0
// after consuming them, so the invariant holds for every graph replay.
__device__ int g_min1[BATCH * N_UP];   // up -> gt
__device__ int g_min2[BATCH * N_GT];   // gt -> up
__device__ int g_min3[BATCH * N_RAD];  // radar -> gt
__device__ float g_part[NRED * 4];     // per-block partials: d1, sqrt1, d2, conf

typedef unsigned long long ull;

__device__ __forceinline__ int enc_key(float d) {
    return __float_as_int(d) ^ 0x80000000;
}
__device__ __forceinline__ float dec_key(int k) {
    return __int_as_float(k ^ 0x80000000);
}

__device__ __forceinline__ ull fma2(ull a, ull b, ull c) {
    ull d;
    asm("fma.rn.f32x2 %0, %1, %2, %3;" : "=l"(d) : "l"(a), "l"(b), "l"(c));
    return d;
}
__device__ __forceinline__ ull add2(ull a, ull b) {
    ull d;
    asm("add.rn.f32x2 %0, %1, %2;" : "=l"(d) : "l"(a), "l"(b));
    return d;
}
__device__ __forceinline__ ull pack2(float lo, float hi) {
    ull d;
    asm("mov.b64 %0, {%1, %2};" : "=l"(d)
        : "r"(__float_as_uint(lo)), "r"(__float_as_uint(hi)));
    return d;
}
__device__ __forceinline__ float2 unpack2(ull v) {
    unsigned lo, hi;
    asm("mov.b64 {%0, %1}, %2;" : "=r"(lo), "=r"(hi) : "l"(v));
    return make_float2(__uint_as_float(lo), __uint_as_float(hi));
}

// ---------------- shared memory (union: fused chamfer vs radar path) --------
struct SmemFused {
    ull   sb[2][128 * 4];     // 2x4KB: dup-packed b tiles {x,x},{y,y},{z,z},{nb,nb}
    float red[2][128 * 17];   // 2x8.5KB: padded reduce arrays (double-buffered)
};
struct SmemRadar {
    ulonglong2 tile[RCHUNK * 2];  // 8KB
};
union SmemAll { SmemFused f; SmemRadar r; };

// ---------------- radar pass (unfused, APT=4) -------------------------------
// min_j (a^2 + b^2 - 2 a.b) = a^2 - 2 * max_j (a.b - 0.5*b^2)
__device__ __forceinline__ void radar_pass(
    ulonglong2* tile,
    const float* __restrict__ apts,
    const float* __restrict__ bpts,
    int* __restrict__ gout,
    int a_start, int b_start)
{
    const int tid = threadIdx.x;

    for (int i = tid; i < RCHUNK; i += NTHREADS) {
        const float* p = bpts + 3 * (b_start + i);
        float x = p[0], y = p[1], z = p[2];
        float nb2 = -0.5f * (x * x + y * y + z * z);
        tile[2 * i]     = make_ulonglong2(pack2(x, x), pack2(y, y));
        tile[2 * i + 1] = make_ulonglong2(pack2(z, z), pack2(nb2, nb2));
    }
    __syncthreads();

    ull AX[2], AY[2], AZ[2];
    float a2[4], smax[4];
#pragma unroll
    for (int p = 0; p < 2; ++p) {
        int i0 = a_start + tid + (2 * p) * NTHREADS;
        int i1 = a_start + tid + (2 * p + 1) * NTHREADS;
        const float* q0 = apts + 3 * i0;
        const float* q1 = apts + 3 * i1;
        float x0 = q0[0], y0 = q0[1], z0 = q0[2];
        float x1 = q1[0], y1 = q1[1], z1 = q1[2];
        AX[p] = pack2(x0, x1); AY[p] = pack2(y0, y1); AZ[p] = pack2(z0, z1);
        a2[2 * p]     = x0 * x0 + y0 * y0 + z0 * z0;
        a2[2 * p + 1] = x1 * x1 + y1 * y1 + z1 * z1;
        smax[2 * p] = smax[2 * p + 1] = -3.0e38f;
    }

#pragma unroll 4
    for (int k = 0; k < RCHUNK; ++k) {
        ulonglong2 p0 = tile[2 * k];
        ulonglong2 p1 = tile[2 * k + 1];
#pragma unroll
        for (int p = 0; p < 2; ++p) {
            ull acc = fma2(AZ[p], p1.x, p1.y);
            acc     = fma2(AY[p], p0.y, acc);
            acc     = fma2(AX[p], p0.x, acc);
            float2 s = unpack2(acc);
            smax[2 * p]     = fmaxf(smax[2 * p], s.x);
            smax[2 * p + 1] = fmaxf(smax[2 * p + 1], s.y);
        }
    }

#pragma unroll
    for (int j = 0; j < 4; ++j) {
        int idx = a_start + tid + j * NTHREADS;
        float d = fmaxf(fmaf(-2.0f, smax[j], a2[j]), 0.0f);
        atomicMin(gout + idx, enc_key(d));
    }
}

// ---------------- b-tile loader ---------------------------------------------
__device__ __forceinline__ void load_b_point(ull* sb, const float* __restrict__ Bp,
                                             int chunk, int slot)
{
    const float* p = Bp + 3 * (chunk * 128 + slot);
    float x = p[0], y = p[1], z = p[2];
    float nb = -0.5f * (x * x + y * y + z * z);
    ull* d = &sb[slot * 4];
    d[0] = pack2(x, x); d[1] = pack2(y, y);
    d[2] = pack2(z, z); d[3] = pack2(nb, nb);
}

// ---------------- pairs kernel ----------------------------------------------
// blocks [0,1024):     fused chamfer up<->gt. Block = (batch, ablk of 64 up, bhalf).
//                      32 chunks of 128 gt; double-buffered sb+red; ONE sync/chunk.
//                      Per phase: low 128 threads reduce cols of chunk c while
//                      high 128 threads prefetch chunk c+2 into the freed buffer.
// blocks [1024,1152):  radar -> gt, unfused, 256-b chunks (same work per block).
__global__ void __launch_bounds__(NTHREADS, 4)
pairs_kernel(const float* __restrict__ pc_up,
             const float* __restrict__ pc2,
             const float* __restrict__ pc3)
{
    __shared__ SmemAll sm;
    const int tid = threadIdx.x;
    const int bid = blockIdx.x;

    if (bid < 1024) {
        const int batch = bid >> 8;          // 256 blocks per batch
        const int r2    = bid & 255;
        const int ablk  = r2 >> 1;           // 0..127 (64 up-points each)
        const int bhalf = r2 & 1;
        const float* Ap = pc_up + (batch * N_UP + ablk * 64) * 3;
        const float* Bp = pc2   + (batch * N_GT + bhalf * 4096) * 3;
        const int ta = tid & 15;   // a-group (4 a-points each)
        const int tb = tid >> 4;   // b-group (8 b-points each)

        // Thread's 4 a-points as 2 packed pairs; symmetric score needs -a^2/2.
        ull AX[2], AY[2], AZ[2], NA[2];
        float rowmax[4];
#pragma unroll
        for (int p = 0; p < 2; ++p) {
            const float* q0 = Ap + 3 * (ta * 4 + 2 * p);
            float x0 = q0[0], y0 = q0[1], z0 = q0[2];
            float x1 = q0[3], y1 = q0[4], z1 = q0[5];
            AX[p] = pack2(x0, x1); AY[p] = pack2(y0, y1); AZ[p] = pack2(z0, z1);
            NA[p] = pack2(-0.5f * (x0 * x0 + y0 * y0 + z0 * z0),
                          -0.5f * (x1 * x1 + y1 * y1 + z1 * z1));
            rowmax[2 * p] = rowmax[2 * p + 1] = -3.0e38f;
        }

        // Preamble: load chunks 0 and 1 (all 256 threads, one b-point each).
        load_b_point(sm.f.sb[tid >> 7], Bp, tid >> 7, tid & 127);
        __syncthreads();

        for (int chunk = 0; chunk < 32; ++chunk) {
            const int buf = chunk & 1;
            float colmax[8];
#pragma unroll
            for (int j = 0; j < 8; ++j) colmax[j] = -3.0e38f;

#pragma unroll
            for (int j = 0; j < 8; ++j) {
                const ull* bb = &sm.f.sb[buf][(tb * 8 + j) * 4];
                ull bx = bb[0], by = bb[1], bz = bb[2], nb = bb[3];
#pragma unroll
                for (int p = 0; p < 2; ++p) {
                    ull acc = fma2(AZ[p], bz, nb);
                    acc     = fma2(AY[p], by, acc);
                    acc     = fma2(AX[p], bx, acc);
                    ull s   = add2(acc, NA[p]);          // s = a.b - a^2/2 - b^2/2 = -d/2
                    float2 f = unpack2(s);
                    rowmax[2 * p]     = fmaxf(rowmax[2 * p],     f.x);
                    rowmax[2 * p + 1] = fmaxf(rowmax[2 * p + 1], f.y);
                    colmax[j] = fmaxf(colmax[j], f.x);
                    colmax[j] = fmaxf(colmax[j], f.y);
                }
            }

            // column (gt->up) partials across the 16 ta-groups
#pragma unroll
            for (int j = 0; j < 8; ++j)
                sm.f.red[buf][(tb * 8 + j) * 17 + ta] = colmax[j];
            __syncthreads();   // ONLY sync this chunk: red[buf] complete;
                               // sb[buf] reads done (free for chunk+2 prefetch)

            if (tid < 128) {
                // col reduce + global atomic (low half)
                const float* row = &sm.f.red[buf][tid * 17];
                float m = row[0];
#pragma unroll
                for (int i = 1; i < 16; ++i) m = fmaxf(m, row[i]);
                float d = fmaxf(-2.0f * m, 0.0f);
                atomicMin(g_min2 + batch * N_GT + bhalf * 4096 + chunk * 128 + tid,
                          enc_key(d));
            } else if (chunk + 2 < 32) {
                // prefetch chunk+2 into the buffer compute just vacated
                load_b_point(sm.f.sb[buf], Bp, chunk + 2, tid - 128);
            }
            // no second sync: next compute reads sb[buf^1] and writes red[buf^1],
            // both untouched by this phase; ordering proven by per-chunk barrier.
        }

        // row (up->gt) reduce across the 16 tb-groups.
        // red[0] last read at chunk 30's phase, strictly before the chunk-31
        // barrier every thread has passed -> safe to overwrite without a sync.
#pragma unroll
        for (int j = 0; j < 4; ++j)
            sm.f.red[0][(ta * 4 + j) * 17 + tb] = rowmax[j];
        __syncthreads();
        if (tid < 64) {
            const float* row = &sm.f.red[0][tid * 17];
            float m = row[0];
#pragma unroll
            for (int i = 1; i < 16; ++i) m = fmaxf(m, row[i]);
            float d = fmaxf(-2.0f * m, 0.0f);
            atomicMin(g_min1 + batch * N_UP + ablk * 64 + tid, enc_key(d));
        }
    } else {
        // radar -> gt: 128 blocks = 4 batches x 32 chunks of 256 gt
        const int r = bid - 1024;
        const int batch = r >> 5;
        const int g = r & 31;
        radar_pass(sm.r.tile, pc3, pc2 + batch * N_GT * 3, g_min3,
                   batch * N_RAD, g * RCHUNK);
    }
}

// ---------------- stage-1 reduction: 64 blocks, fixed slices ----------------
// Each block consumes a fixed slice of each min-array (and resets it to 0),
// reduces in a fixed-order smem tree, writes 4 partials. Deterministic.
__global__ void __launch_bounds__(NTHREADS)
reduce_partial(const float* __restrict__ conf)
{
    const int tid = threadIdx.x;
    const int bid = blockIdx.x;
    float s_d1 = 0.f, s_sqrt1 = 0.f, s_d2 = 0.f, s_conf = 0.f;
    const int4 zero4 = make_int4(0, 0, 0, 0);

    // v1: 8192 int4 total -> 128 per block
    {
        int4* v1 = (int4*)g_min1 + bid * 128;
        if (tid < 128) {
            int4 v = v1[tid];
            float d0 = dec_key(v.x), d1 = dec_key(v.y);
            float d2 = dec_key(v.z), d3 = dec_key(v.w);
            s_d1 = (d0 + d1) + (d2 + d3);
            s_sqrt1 = (sqrtf(d0) + sqrtf(d1)) + (sqrtf(d2) + sqrtf(d3));
            v1[tid] = zero4;
        }
    }
    // v2: 8192 int4 total -> 128 per block
    {
        int4* v2 = (int4*)g_min2 + bid * 128;
        if (tid < 128) {
            int4 v = v2[tid];
            s_d2 = (dec_key(v.x) + dec_key(v.y)) + (dec_key(v.z) + dec_key(v.w));
            v2[tid] = zero4;
        }
    }
    // v3: 1024 int4 total -> 16 per block
    {
        int4*         v3 = (int4*)g_min3 + bid * 16;
        const float4* c4 = (const float4*)conf + bid * 16;
        if (tid < 16) {
            int4 v = v3[tid];
            float4 c = c4[tid];
            float e0 = c.x - expf(-sqrtf(dec_key(v.x)));
            float e1 = c.y - expf(-sqrtf(dec_key(v.y)));
            float e2 = c.z - expf(-sqrtf(dec_key(v.z)));
            float e3 = c.w - expf(-sqrtf(dec_key(v.w)));
            s_conf = (e0 * e0 + e1 * e1) + (e2 * e2 + e3 * e3);
            v3[tid] = zero4;
        }
    }

    __shared__ float r1[NTHREADS], r2[NTHREADS], r3[NTHREADS], r4[NTHREADS];
    r1[tid] = s_d1; r2[tid] = s_sqrt1; r3[tid] = s_d2; r4[tid] = s_conf;
    __syncthreads();
    for (int s = NTHREADS / 2; s > 0; s >>= 1) {
        if (tid < s) {
            r1[tid] += r1[tid + s];
            r2[tid] += r2[tid + s];
            r3[tid] += r3[tid + s];
            r4[tid] += r4[tid + s];
        }
        __syncthreads();
    }
    if (tid == 0) {
        g_part[bid * 4 + 0] = r1[0];
        g_part[bid * 4 + 1] = r2[0];
        g_part[bid * 4 + 2] = r3[0];
        g_part[bid * 4 + 3] = r4[0];
    }
}

// ---------------- stage-2: combine 64 partials (fixed-order tree) -----------
__global__ void __launch_bounds__(64)
reduce_final(float* __restrict__ out)
{
    const int tid = threadIdx.x;
    __shared__ float r1[64], r2[64], r3[64], r4[64];
    r1[tid] = g_part[tid * 4 + 0];
    r2[tid] = g_part[tid * 4 + 1];
    r3[tid] = g_part[tid * 4 + 2];
    r4[tid] = g_part[tid * 4 + 3];
    __syncthreads();
    for (int s = 32; s > 0; s >>= 1) {
        if (tid < s) {
            r1[tid] += r1[tid + s];
            r2[tid] += r2[tid + s];
            r3[tid] += r3[tid + s];
            r4[tid] += r4[tid + s];
        }
        __syncthreads();
    }
    if (tid == 0) {
        const float inv_up  = 1.0f / (BATCH * N_UP);
        const float inv_gt  = 1.0f / (BATCH * N_GT);
        const float inv_rad = 1.0f / (BATCH * N_RAD);
        float mean1     = r1[0] * inv_up;
        float mean_sqrt = r2[0] * inv_up;
        float mean2     = r3[0] * inv_gt;
        float conf_loss = r4[0] * inv_rad;
        float chamfer = 0.5f * mean1 + 2.0f * mean2;
        out[0] = 0.5f * chamfer + 0.5f * conf_loss + mean_sqrt;  // ALPHA = 0.5
    }
}

extern "C" void kernel_launch(void* const* d_in, const int* in_sizes, int n_in,
                              void* d_out, int out_size)
{
    (void)in_sizes; (void)n_in; (void)out_size;
    const float* pc_up   = (const float*)d_in[0];
    // d_in[1] = pc_seed (unused by the reference loss)
    const float* pc_conf = (const float*)d_in[2];
    const float* pc2     = (const float*)d_in[3];
    const float* pc3     = (const float*)d_in[4];

    // No init kernel: zero-initialized (or reduce-reset) g_min arrays act as
    // +inf under the sign-flipped key encoding.
    pairs_kernel<<<1152, NTHREADS>>>(pc_up, pc2, pc3);
    reduce_partial<<<NRED, NTHREADS>>>(pc_conf);
    reduce_final<<<1, 64>>>((float*)d_out);
}

// round 10
// speedup vs baseline: 1.0067x; 1.0067x over previous
#include <cuda_runtime.h>

// Problem constants (fixed by setup_inputs)
#define BATCH 4
#define N_UP  8192
#define N_GT  8192
#define N_RAD 1024
#define RCHUNK 256         // radar pass: b-points per block tile
#define NTHREADS 256
#define NRED 64            // partial-reduce blocks

// Running min of squared distance per point, stored as sign-flipped float bits:
//   key = __float_as_int(d) ^ 0x80000000   (d >= 0)
// Keys are negative ints, monotone increasing in d, so zero-initialized state
// (signed 0 > any key) acts as +infinity. reduce_partial resets slots to 0
// after consuming them, so the invariant holds for every graph replay.
__device__ int g_min1[BATCH * N_UP];   // up -> gt
__device__ int g_min2[BATCH * N_GT];   // gt -> up
__device__ int g_min3[BATCH * N_RAD];  // radar -> gt
__device__ float g_part[NRED * 4];     // per-block partials: d1, sqrt1, d2, conf

typedef unsigned long long ull;

__device__ __forceinline__ int enc_key(float d) {
    return __float_as_int(d) ^ 0x80000000;
}
__device__ __forceinline__ float dec_key(int k) {
    return __int_as_float(k ^ 0x80000000);
}

__device__ __forceinline__ ull fma2(ull a, ull b, ull c) {
    ull d;
    asm("fma.rn.f32x2 %0, %1, %2, %3;" : "=l"(d) : "l"(a), "l"(b), "l"(c));
    return d;
}
__device__ __forceinline__ ull add2(ull a, ull b) {
    ull d;
    asm("add.rn.f32x2 %0, %1, %2;" : "=l"(d) : "l"(a), "l"(b));
    return d;
}
__device__ __forceinline__ ull pack2(float lo, float hi) {
    ull d;
    asm("mov.b64 %0, {%1, %2};" : "=l"(d)
        : "r"(__float_as_uint(lo)), "r"(__float_as_uint(hi)));
    return d;
}
__device__ __forceinline__ float2 unpack2(ull v) {
    unsigned lo, hi;
    asm("mov.b64 {%0, %1}, %2;" : "=r"(lo), "=r"(hi) : "l"(v));
    return make_float2(__uint_as_float(lo), __uint_as_float(hi));
}

// ---------------- shared memory (union: fused chamfer vs radar path) --------
struct SmemFused {
    ull   sb[2][128 * 4];     // 2x4KB: dup-packed b tiles {x,x},{y,y},{z,z},{nb,nb}
    float red[2][128 * 17];   // 2x8.5KB: padded reduce arrays (double-buffered)
};
struct SmemRadar {
    ulonglong2 tile[RCHUNK * 2];  // 8KB
};
union SmemAll { SmemFused f; SmemRadar r; };

// ---------------- radar pass (unfused, APT=4) -------------------------------
// min_j (a^2 + b^2 - 2 a.b) = a^2 - 2 * max_j (a.b - 0.5*b^2)
__device__ __forceinline__ void radar_pass(
    ulonglong2* tile,
    const float* __restrict__ apts,
    const float* __restrict__ bpts,
    int* __restrict__ gout,
    int a_start, int b_start)
{
    const int tid = threadIdx.x;

    for (int i = tid; i < RCHUNK; i += NTHREADS) {
        const float* p = bpts + 3 * (b_start + i);
        float x = p[0], y = p[1], z = p[2];
        float nb2 = -0.5f * (x * x + y * y + z * z);
        tile[2 * i]     = make_ulonglong2(pack2(x, x), pack2(y, y));
        tile[2 * i + 1] = make_ulonglong2(pack2(z, z), pack2(nb2, nb2));
    }
    __syncthreads();

    ull AX[2], AY[2], AZ[2];
    float a2[4], smax[4];
#pragma unroll
    for (int p = 0; p < 2; ++p) {
        int i0 = a_start + tid + (2 * p) * NTHREADS;
        int i1 = a_start + tid + (2 * p + 1) * NTHREADS;
        const float* q0 = apts + 3 * i0;
        const float* q1 = apts + 3 * i1;
        float x0 = q0[0], y0 = q0[1], z0 = q0[2];
        float x1 = q1[0], y1 = q1[1], z1 = q1[2];
        AX[p] = pack2(x0, x1); AY[p] = pack2(y0, y1); AZ[p] = pack2(z0, z1);
        a2[2 * p]     = x0 * x0 + y0 * y0 + z0 * z0;
        a2[2 * p + 1] = x1 * x1 + y1 * y1 + z1 * z1;
        smax[2 * p] = smax[2 * p + 1] = -3.0e38f;
    }

#pragma unroll 4
    for (int k = 0; k < RCHUNK; ++k) {
        ulonglong2 p0 = tile[2 * k];
        ulonglong2 p1 = tile[2 * k + 1];
#pragma unroll
        for (int p = 0; p < 2; ++p) {
            ull acc = fma2(AZ[p], p1.x, p1.y);
            acc     = fma2(AY[p], p0.y, acc);
            acc     = fma2(AX[p], p0.x, acc);
            float2 s = unpack2(acc);
            smax[2 * p]     = fmaxf(smax[2 * p], s.x);
            smax[2 * p + 1] = fmaxf(smax[2 * p + 1], s.y);
        }
    }

#pragma unroll
    for (int j = 0; j < 4; ++j) {
        int idx = a_start + tid + j * NTHREADS;
        float d = fmaxf(fmaf(-2.0f, smax[j], a2[j]), 0.0f);
        atomicMin(gout + idx, enc_key(d));
    }
}

// ---------------- b-tile loader ---------------------------------------------
__device__ __forceinline__ void load_b_point(ull* sb, const float* __restrict__ Bp,
                                             int chunk, int slot)
{
    const float* p = Bp + 3 * (chunk * 128 + slot);
    float x = p[0], y = p[1], z = p[2];
    float nb = -0.5f * (x * x + y * y + z * z);
    ull* d = &sb[slot * 4];
    d[0] = pack2(x, x); d[1] = pack2(y, y);
    d[2] = pack2(z, z); d[3] = pack2(nb, nb);
}

// ---------------- pairs kernel ----------------------------------------------
// blocks [0,512):     fused chamfer up<->gt. Block = (batch, ablk of 128 up, bhalf).
//                     32 chunks of 128 gt; APT=8; double-buffered sb+red;
//                     ONE sync/chunk: low half reduces cols of chunk c while
//                     high half prefetches chunk c+2 into the freed buffer.
// blocks [512,640):   radar -> gt, unfused, 256-b chunks.
__global__ void __launch_bounds__(NTHREADS, 4)
pairs_kernel(const float* __restrict__ pc_up,
             const float* __restrict__ pc2,
             const float* __restrict__ pc3)
{
    __shared__ SmemAll sm;
    const int tid = threadIdx.x;
    const int bid = blockIdx.x;

    if (bid < 512) {
        const int batch = bid >> 7;
        const int r2    = bid & 127;
        const int ablk  = r2 >> 1;
        const int bhalf = r2 & 1;
        const float* Ap = pc_up + (batch * N_UP + ablk * 128) * 3;
        const float* Bp = pc2   + (batch * N_GT + bhalf * 4096) * 3;
        const int ta = tid & 15;   // a-group (8 a-points each)
        const int tb = tid >> 4;   // b-group (8 b-points each)

        // Thread's 8 a-points as 4 packed pairs; symmetric score needs -a^2/2.
        ull AX[4], AY[4], AZ[4], NA[4];
        float rowmax[8];
#pragma unroll
        for (int p = 0; p < 4; ++p) {
            const float* q0 = Ap + 3 * (ta * 8 + 2 * p);
            float x0 = q0[0], y0 = q0[1], z0 = q0[2];
            float x1 = q0[3], y1 = q0[4], z1 = q0[5];
            AX[p] = pack2(x0, x1); AY[p] = pack2(y0, y1); AZ[p] = pack2(z0, z1);
            NA[p] = pack2(-0.5f * (x0 * x0 + y0 * y0 + z0 * z0),
                          -0.5f * (x1 * x1 + y1 * y1 + z1 * z1));
            rowmax[2 * p] = rowmax[2 * p + 1] = -3.0e38f;
        }

        // Preamble: load chunks 0 and 1 (all 256 threads, one b-point each).
        load_b_point(sm.f.sb[tid >> 7], Bp, tid >> 7, tid & 127);
        __syncthreads();

        for (int chunk = 0; chunk < 32; ++chunk) {
            const int buf = chunk & 1;
            float colmax[8];
#pragma unroll
            for (int j = 0; j < 8; ++j) colmax[j] = -3.0e38f;

#pragma unroll
            for (int j = 0; j < 8; ++j) {
                const ull* bb = &sm.f.sb[buf][(tb * 8 + j) * 4];
                ull bx = bb[0], by = bb[1], bz = bb[2], nb = bb[3];
#pragma unroll
                for (int p = 0; p < 4; ++p) {
                    ull acc = fma2(AZ[p], bz, nb);
                    acc     = fma2(AY[p], by, acc);
                    acc     = fma2(AX[p], bx, acc);
                    ull s   = add2(acc, NA[p]);          // s = a.b - a^2/2 - b^2/2 = -d/2
                    float2 f = unpack2(s);
                    rowmax[2 * p]     = fmaxf(rowmax[2 * p],     f.x);
                    rowmax[2 * p + 1] = fmaxf(rowmax[2 * p + 1], f.y);
                    colmax[j] = fmaxf(colmax[j], f.x);
                    colmax[j] = fmaxf(colmax[j], f.y);
                }
            }

            // column (gt->up) partials across the 16 ta-groups
#pragma unroll
            for (int j = 0; j < 8; ++j)
                sm.f.red[buf][(tb * 8 + j) * 17 + ta] = colmax[j];
            __syncthreads();   // ONLY sync this chunk: red[buf] complete;
                               // sb[buf] reads done (free for chunk+2 prefetch)

            if (tid < 128) {
                // col reduce + global atomic (low half)
                const float* row = &sm.f.red[buf][tid * 17];
                float m = row[0];
#pragma unroll
                for (int i = 1; i < 16; ++i) m = fmaxf(m, row[i]);
                float d = fmaxf(-2.0f * m, 0.0f);
                atomicMin(g_min2 + batch * N_GT + bhalf * 4096 + chunk * 128 + tid,
                          enc_key(d));
            } else if (chunk + 2 < 32) {
                // prefetch chunk+2 into the buffer compute just vacated
                load_b_point(sm.f.sb[buf], Bp, chunk + 2, tid - 128);
            }
            // no second sync: next compute reads sb[buf^1] and writes red[buf^1],
            // both untouched by this phase; ordering proven by per-chunk barrier.
        }

        // row (up->gt) reduce across the 16 tb-groups.
        // red[0]'s chunk-30 readers finished before they reached the chunk-31
        // barrier, which all threads have passed -> safe to overwrite.
#pragma unroll
        for (int j = 0; j < 8; ++j)
            sm.f.red[0][(ta * 8 + j) * 17 + tb] = rowmax[j];
        __syncthreads();
        if (tid < 128) {
            const float* row = &sm.f.red[0][tid * 17];
            float m = row[0];
#pragma unroll
            for (int i = 1; i < 16; ++i) m = fmaxf(m, row[i]);
            float d = fmaxf(-2.0f * m, 0.0f);
            atomicMin(g_min1 + batch * N_UP + ablk * 128 + tid, enc_key(d));
        }
    } else {
        // radar -> gt: 128 blocks = 4 batches x 32 chunks of 256 gt
        const int r = bid - 512;
        const int batch = r >> 5;
        const int g = r & 31;
        radar_pass(sm.r.tile, pc3, pc2 + batch * N_GT * 3, g_min3,
                   batch * N_RAD, g * RCHUNK);
    }
}

// ---------------- stage-1 reduction: 64 blocks, fixed slices ----------------
// Each block consumes a fixed slice of each min-array (and resets it to 0),
// reduces in a fixed-order smem tree, writes 4 partials. Deterministic.
__global__ void __launch_bounds__(NTHREADS)
reduce_partial(const float* __restrict__ conf)
{
    const int tid = threadIdx.x;
    const int bid = blockIdx.x;
    float s_d1 = 0.f, s_sqrt1 = 0.f, s_d2 = 0.f, s_conf = 0.f;
    const int4 zero4 = make_int4(0, 0, 0, 0);

    // v1: 8192 int4 total -> 128 per block
    {
        int4* v1 = (int4*)g_min1 + bid * 128;
        if (tid < 128) {
            int4 v = v1[tid];
            float d0 = dec_key(v.x), d1 = dec_key(v.y);
            float d2 = dec_key(v.z), d3 = dec_key(v.w);
            s_d1 = (d0 + d1) + (d2 + d3);
            s_sqrt1 = (sqrtf(d0) + sqrtf(d1)) + (sqrtf(d2) + sqrtf(d3));
            v1[tid] = zero4;
        }
    }
    // v2: 8192 int4 total -> 128 per block
    {
        int4* v2 = (int4*)g_min2 + bid * 128;
        if (tid < 128) {
            int4 v = v2[tid];
            s_d2 = (dec_key(v.x) + dec_key(v.y)) + (dec_key(v.z) + dec_key(v.w));
            v2[tid] = zero4;
        }
    }
    // v3: 1024 int4 total -> 16 per block
    {
        int4*         v3 = (int4*)g_min3 + bid * 16;
        const float4* c4 = (const float4*)conf + bid * 16;
        if (tid < 16) {
            int4 v = v3[tid];
            float4 c = c4[tid];
            float e0 = c.x - expf(-sqrtf(dec_key(v.x)));
            float e1 = c.y - expf(-sqrtf(dec_key(v.y)));
            float e2 = c.z - expf(-sqrtf(dec_key(v.z)));
            float e3 = c.w - expf(-sqrtf(dec_key(v.w)));
            s_conf = (e0 * e0 + e1 * e1) + (e2 * e2 + e3 * e3);
            v3[tid] = zero4;
        }
    }

    __shared__ float r1[NTHREADS], r2[NTHREADS], r3[NTHREADS], r4[NTHREADS];
    r1[tid] = s_d1; r2[tid] = s_sqrt1; r3[tid] = s_d2; r4[tid] = s_conf;
    __syncthreads();
    for (int s = NTHREADS / 2; s > 0; s >>= 1) {
        if (tid < s) {
            r1[tid] += r1[tid + s];
            r2[tid] += r2[tid + s];
            r3[tid] += r3[tid + s];
            r4[tid] += r4[tid + s];
        }
        __syncthreads();
    }
    if (tid == 0) {
        g_part[bid * 4 + 0] = r1[0];
        g_part[bid * 4 + 1] = r2[0];
        g_part[bid * 4 + 2] = r3[0];
        g_part[bid * 4 + 3] = r4[0];
    }
}

// ---------------- stage-2: combine 64 partials (fixed-order tree) -----------
__global__ void __launch_bounds__(64)
reduce_final(float* __restrict__ out)
{
    const int tid = threadIdx.x;
    __shared__ float r1[64], r2[64], r3[64], r4[64];
    r1[tid] = g_part[tid * 4 + 0];
    r2[tid] = g_part[tid * 4 + 1];
    r3[tid] = g_part[tid * 4 + 2];
    r4[tid] = g_part[tid * 4 + 3];
    __syncthreads();
    for (int s = 32; s > 0; s >>= 1) {
        if (tid < s) {
            r1[tid] += r1[tid + s];
            r2[tid] += r2[tid + s];
            r3[tid] += r3[tid + s];
            r4[tid] += r4[tid + s];
        }
        __syncthreads();
    }
    if (tid == 0) {
        const float inv_up  = 1.0f / (BATCH * N_UP);
        const float inv_gt  = 1.0f / (BATCH * N_GT);
        const float inv_rad = 1.0f / (BATCH * N_RAD);
        float mean1     = r1[0] * inv_up;
        float mean_sqrt = r2[0] * inv_up;
        float mean2     = r3[0] * inv_gt;
        float conf_loss = r4[0] * inv_rad;
        float chamfer = 0.5f * mean1 + 2.0f * mean2;
        out[0] = 0.5f * chamfer + 0.5f * conf_loss + mean_sqrt;  // ALPHA = 0.5
    }
}

extern "C" void kernel_launch(void* const* d_in, const int* in_sizes, int n_in,
                              void* d_out, int out_size)
{
    (void)in_sizes; (void)n_in; (void)out_size;
    const float* pc_up   = (const float*)d_in[0];
    // d_in[1] = pc_seed (unused by the reference loss)
    const float* pc_conf = (const float*)d_in[2];
    const float* pc2     = (const float*)d_in[3];
    const float* pc3     = (const float*)d_in[4];

    // No init kernel: zero-initialized (or reduce-reset) g_min arrays act as
    // +inf under the sign-flipped key encoding.
    pairs_kernel<<<640, NTHREADS>>>(pc_up, pc2, pc3);
    reduce_partial<<<NRED, NTHREADS>>>(pc_conf);
    reduce_final<<<1, 64>>>((float*)d_out);
}

// round 11
// speedup vs baseline: 1.1410x; 1.1334x over previous
#include <cuda_runtime.h>

// Problem constants (fixed by setup_inputs)
#define BATCH 4
#define N_UP  8192
#define N_GT  8192
#define N_RAD 1024
#define RCHUNK 256         // radar pass: b-points per block tile
#define NTHREADS 256
#define NRED 64            // partial-reduce blocks

// Running min of squared distance per point, stored as sign-flipped float bits:
//   key = __float_as_int(d) ^ 0x80000000   (d >= 0)
// Keys are negative ints, monotone increasing in d, so zero-initialized state
// (signed 0 > any key) acts as +infinity. reduce_partial resets slots to 0
// after consuming them, so the invariant holds for every graph replay.
__device__ int g_min1[BATCH * N_UP];   // up -> gt
__device__ int g_min2[BATCH * N_GT];   // gt -> up
__device__ int g_min3[BATCH * N_RAD];  // radar -> gt
__device__ float g_part[NRED * 4];     // per-block partials: d1, sqrt1, d2, conf

typedef unsigned long long ull;

__device__ __forceinline__ int enc_key(float d) {
    return __float_as_int(d) ^ 0x80000000;
}
__device__ __forceinline__ float dec_key(int k) {
    return __int_as_float(k ^ 0x80000000);
}

__device__ __forceinline__ ull fma2(ull a, ull b, ull c) {
    ull d;
    asm("fma.rn.f32x2 %0, %1, %2, %3;" : "=l"(d) : "l"(a), "l"(b), "l"(c));
    return d;
}
__device__ __forceinline__ ull add2(ull a, ull b) {
    ull d;
    asm("add.rn.f32x2 %0, %1, %2;" : "=l"(d) : "l"(a), "l"(b));
    return d;
}
__device__ __forceinline__ ull pack2(float lo, float hi) {
    ull d;
    asm("mov.b64 %0, {%1, %2};" : "=l"(d)
        : "r"(__float_as_uint(lo)), "r"(__float_as_uint(hi)));
    return d;
}
__device__ __forceinline__ float2 unpack2(ull v) {
    unsigned lo, hi;
    asm("mov.b64 {%0, %1}, %2;" : "=r"(lo), "=r"(hi) : "l"(v));
    return make_float2(__uint_as_float(lo), __uint_as_float(hi));
}

// ---------------- shared memory (union: fused chamfer vs radar path) --------
struct SmemFused {
    ull   sb[2][128 * 4];     // 2x4KB: dup-packed b tiles {x,x},{y,y},{z,z},{nb,nb}
    float red[2][128 * 17];   // 2x8.5KB: padded reduce arrays (double-buffered)
};
struct SmemRadar {
    ulonglong2 tile[RCHUNK * 2];  // 8KB
};
union SmemAll { SmemFused f; SmemRadar r; };

// ---------------- radar pass (unfused, APT=4) -------------------------------
// min_j (a^2 + b^2 - 2 a.b) = a^2 - 2 * max_j (a.b - 0.5*b^2)
__device__ __forceinline__ void radar_pass(
    ulonglong2* tile,
    const float* __restrict__ apts,
    const float* __restrict__ bpts,
    int* __restrict__ gout,
    int a_start, int b_start)
{
    const int tid = threadIdx.x;

    for (int i = tid; i < RCHUNK; i += NTHREADS) {
        const float* p = bpts + 3 * (b_start + i);
        float x = p[0], y = p[1], z = p[2];
        float nb2 = -0.5f * (x * x + y * y + z * z);
        tile[2 * i]     = make_ulonglong2(pack2(x, x), pack2(y, y));
        tile[2 * i + 1] = make_ulonglong2(pack2(z, z), pack2(nb2, nb2));
    }
    __syncthreads();

    ull AX[2], AY[2], AZ[2];
    float a2[4], smax[4];
#pragma unroll
    for (int p = 0; p < 2; ++p) {
        int i0 = a_start + tid + (2 * p) * NTHREADS;
        int i1 = a_start + tid + (2 * p + 1) * NTHREADS;
        const float* q0 = apts + 3 * i0;
        const float* q1 = apts + 3 * i1;
        float x0 = q0[0], y0 = q0[1], z0 = q0[2];
        float x1 = q1[0], y1 = q1[1], z1 = q1[2];
        AX[p] = pack2(x0, x1); AY[p] = pack2(y0, y1); AZ[p] = pack2(z0, z1);
        a2[2 * p]     = x0 * x0 + y0 * y0 + z0 * z0;
        a2[2 * p + 1] = x1 * x1 + y1 * y1 + z1 * z1;
        smax[2 * p] = smax[2 * p + 1] = -3.0e38f;
    }

#pragma unroll 4
    for (int k = 0; k < RCHUNK; ++k) {
        ulonglong2 p0 = tile[2 * k];
        ulonglong2 p1 = tile[2 * k + 1];
#pragma unroll
        for (int p = 0; p < 2; ++p) {
            ull acc = fma2(AZ[p], p1.x, p1.y);
            acc     = fma2(AY[p], p0.y, acc);
            acc     = fma2(AX[p], p0.x, acc);
            float2 s = unpack2(acc);
            smax[2 * p]     = fmaxf(smax[2 * p], s.x);
            smax[2 * p + 1] = fmaxf(smax[2 * p + 1], s.y);
        }
    }

#pragma unroll
    for (int j = 0; j < 4; ++j) {
        int idx = a_start + tid + j * NTHREADS;
        float d = fmaxf(fmaf(-2.0f, smax[j], a2[j]), 0.0f);
        atomicMin(gout + idx, enc_key(d));
    }
}

// ---------------- b-tile loader ---------------------------------------------
__device__ __forceinline__ void load_b_point(ull* sb, const float* __restrict__ Bp,
                                             int chunk, int slot)
{
    const float* p = Bp + 3 * (chunk * 128 + slot);
    float x = p[0], y = p[1], z = p[2];
    float nb = -0.5f * (x * x + y * y + z * z);
    ull* d = &sb[slot * 4];
    d[0] = pack2(x, x); d[1] = pack2(y, y);
    d[2] = pack2(z, z); d[3] = pack2(nb, nb);
}

// ---------------- pairs kernel ----------------------------------------------
// All 1152 blocks do 262144 pair evaluations (equal duration):
// blocks [0,1024):     fused chamfer up<->gt. Block = (batch, ablk of 128 up,
//                      gt-quarter of 2048). 16 chunks of 128 gt; APT=8;
//                      double-buffered sb+red; ONE sync/chunk; low half
//                      reduces cols of chunk c while high half prefetches
//                      chunk c+2 into the freed buffer.
// blocks [1024,1152):  radar -> gt, unfused, 256-gt chunks.
// Grid = 1152 = 1.95 waves at 4 blocks/SM (592 slots) -> ~97% slot util.
__global__ void __launch_bounds__(NTHREADS, 4)
pairs_kernel(const float* __restrict__ pc_up,
             const float* __restrict__ pc2,
             const float* __restrict__ pc3)
{
    __shared__ SmemAll sm;
    const int tid = threadIdx.x;
    const int bid = blockIdx.x;

    if (bid < 1024) {
        const int batch = bid >> 8;          // 256 blocks per batch
        const int r2    = bid & 255;
        const int ablk  = r2 >> 2;           // 0..63 (128 up-points each)
        const int bq    = r2 & 3;            // gt quarter (2048 each)
        const float* Ap = pc_up + (batch * N_UP + ablk * 128) * 3;
        const float* Bp = pc2   + (batch * N_GT + bq * 2048) * 3;
        const int ta = tid & 15;   // a-group (8 a-points each)
        const int tb = tid >> 4;   // b-group (8 b-points each)

        // Thread's 8 a-points as 4 packed pairs; symmetric score needs -a^2/2.
        ull AX[4], AY[4], AZ[4], NA[4];
        float rowmax[8];
#pragma unroll
        for (int p = 0; p < 4; ++p) {
            const float* q0 = Ap + 3 * (ta * 8 + 2 * p);
            float x0 = q0[0], y0 = q0[1], z0 = q0[2];
            float x1 = q0[3], y1 = q0[4], z1 = q0[5];
            AX[p] = pack2(x0, x1); AY[p] = pack2(y0, y1); AZ[p] = pack2(z0, z1);
            NA[p] = pack2(-0.5f * (x0 * x0 + y0 * y0 + z0 * z0),
                          -0.5f * (x1 * x1 + y1 * y1 + z1 * z1));
            rowmax[2 * p] = rowmax[2 * p + 1] = -3.0e38f;
        }

        // Preamble: load chunks 0 and 1 (all 256 threads, one b-point each).
        load_b_point(sm.f.sb[tid >> 7], Bp, tid >> 7, tid & 127);
        __syncthreads();

        for (int chunk = 0; chunk < 16; ++chunk) {
            const int buf = chunk & 1;

#pragma unroll
            for (int j = 0; j < 8; ++j) {
                const ull* bb = &sm.f.sb[buf][(tb * 8 + j) * 4];
                ull bx = bb[0], by = bb[1], bz = bb[2], nb = bb[3];
                float t[4];
#pragma unroll
                for (int p = 0; p < 4; ++p) {
                    ull acc = fma2(AZ[p], bz, nb);
                    acc     = fma2(AY[p], by, acc);
                    acc     = fma2(AX[p], bx, acc);
                    ull s   = add2(acc, NA[p]);          // s = a.b - a^2/2 - b^2/2 = -d/2
                    float2 f = unpack2(s);
                    rowmax[2 * p]     = fmaxf(rowmax[2 * p],     f.x);
                    rowmax[2 * p + 1] = fmaxf(rowmax[2 * p + 1], f.y);
                    t[p] = fmaxf(f.x, f.y);
                }
                // column partial for this b-point (single-shot per chunk, tree)
                float cj = fmaxf(fmaxf(t[0], t[1]), fmaxf(t[2], t[3]));
                sm.f.red[buf][(tb * 8 + j) * 17 + ta] = cj;
            }
            __syncthreads();   // ONLY sync this chunk: red[buf] complete;
                               // sb[buf] reads done (free for chunk+2 prefetch)

            if (tid < 128) {
                // col reduce + global atomic (low half)
                const float* row = &sm.f.red[buf][tid * 17];
                float m = row[0];
#pragma unroll
                for (int i = 1; i < 16; ++i) m = fmaxf(m, row[i]);
                float d = fmaxf(-2.0f * m, 0.0f);
                atomicMin(g_min2 + batch * N_GT + bq * 2048 + chunk * 128 + tid,
                          enc_key(d));
            } else if (chunk + 2 < 16) {
                // prefetch chunk+2 into the buffer compute just vacated
                load_b_point(sm.f.sb[buf], Bp, chunk + 2, tid - 128);
            }
            // no second sync: next compute reads sb[buf^1] and writes red[buf^1],
            // both untouched by this phase; ordering proven by per-chunk barrier.
        }

        // row (up->gt) reduce across the 16 tb-groups.
        // red[0]'s chunk-14 readers finished before the chunk-15 barrier,
        // which all threads have passed -> safe to overwrite.
#pragma unroll
        for (int j = 0; j < 8; ++j)
            sm.f.red[0][(ta * 8 + j) * 17 + tb] = rowmax[j];
        __syncthreads();
        if (tid < 128) {
            const float* row = &sm.f.red[0][tid * 17];
            float m = row[0];
#pragma unroll
            for (int i = 1; i < 16; ++i) m = fmaxf(m, row[i]);
            float d = fmaxf(-2.0f * m, 0.0f);
            atomicMin(g_min1 + batch * N_UP + ablk * 128 + tid, enc_key(d));
        }
    } else {
        // radar -> gt: 128 blocks = 4 batches x 32 chunks of 256 gt
        const int r = bid - 1024;
        const int batch = r >> 5;
        const int g = r & 31;
        radar_pass(sm.r.tile, pc3, pc2 + batch * N_GT * 3, g_min3,
                   batch * N_RAD, g * RCHUNK);
    }
}

// ---------------- stage-1 reduction: 64 blocks, fixed slices ----------------
// Each block consumes a fixed slice of each min-array (and resets it to 0),
// reduces in a fixed-order smem tree, writes 4 partials. Deterministic.
__global__ void __launch_bounds__(NTHREADS)
reduce_partial(const float* __restrict__ conf)
{
    const int tid = threadIdx.x;
    const int bid = blockIdx.x;
    float s_d1 = 0.f, s_sqrt1 = 0.f, s_d2 = 0.f, s_conf = 0.f;
    const int4 zero4 = make_int4(0, 0, 0, 0);

    // v1: 8192 int4 total -> 128 per block
    {
        int4* v1 = (int4*)g_min1 + bid * 128;
        if (tid < 128) {
            int4 v = v1[tid];
            float d0 = dec_key(v.x), d1 = dec_key(v.y);
            float d2 = dec_key(v.z), d3 = dec_key(v.w);
            s_d1 = (d0 + d1) + (d2 + d3);
            s_sqrt1 = (sqrtf(d0) + sqrtf(d1)) + (sqrtf(d2) + sqrtf(d3));
            v1[tid] = zero4;
        }
    }
    // v2: 8192 int4 total -> 128 per block
    {
        int4* v2 = (int4*)g_min2 + bid * 128;
        if (tid < 128) {
            int4 v = v2[tid];
            s_d2 = (dec_key(v.x) + dec_key(v.y)) + (dec_key(v.z) + dec_key(v.w));
            v2[tid] = zero4;
        }
    }
    // v3: 1024 int4 total -> 16 per block
    {
        int4*         v3 = (int4*)g_min3 + bid * 16;
        const float4* c4 = (const float4*)conf + bid * 16;
        if (tid < 16) {
            int4 v = v3[tid];
            float4 c = c4[tid];
            float e0 = c.x - expf(-sqrtf(dec_key(v.x)));
            float e1 = c.y - expf(-sqrtf(dec_key(v.y)));
            float e2 = c.z - expf(-sqrtf(dec_key(v.z)));
            float e3 = c.w - expf(-sqrtf(dec_key(v.w)));
            s_conf = (e0 * e0 + e1 * e1) + (e2 * e2 + e3 * e3);
            v3[tid] = zero4;
        }
    }

    __shared__ float r1[NTHREADS], r2[NTHREADS], r3[NTHREADS], r4[NTHREADS];
    r1[tid] = s_d1; r2[tid] = s_sqrt1; r3[tid] = s_d2; r4[tid] = s_conf;
    __syncthreads();
    for (int s = NTHREADS / 2; s > 0; s >>= 1) {
        if (tid < s) {
            r1[tid] += r1[tid + s];
            r2[tid] += r2[tid + s];
            r3[tid] += r3[tid + s];
            r4[tid] += r4[tid + s];
        }
        __syncthreads();
    }
    if (tid == 0) {
        g_part[bid * 4 + 0] = r1[0];
        g_part[bid * 4 + 1] = r2[0];
        g_part[bid * 4 + 2] = r3[0];
        g_part[bid * 4 + 3] = r4[0];
    }
}

// ---------------- stage-2: combine 64 partials (fixed-order tree) -----------
__global__ void __launch_bounds__(64)
reduce_final(float* __restrict__ out)
{
    const int tid = threadIdx.x;
    __shared__ float r1[64], r2[64], r3[64], r4[64];
    r1[tid] = g_part[tid * 4 + 0];
    r2[tid] = g_part[tid * 4 + 1];
    r3[tid] = g_part[tid * 4 + 2];
    r4[tid] = g_part[tid * 4 + 3];
    __syncthreads();
    for (int s = 32; s > 0; s >>= 1) {
        if (tid < s) {
            r1[tid] += r1[tid + s];
            r2[tid] += r2[tid + s];
            r3[tid] += r3[tid + s];
            r4[tid] += r4[tid + s];
        }
        __syncthreads();
    }
    if (tid == 0) {
        const float inv_up  = 1.0f / (BATCH * N_UP);
        const float inv_gt  = 1.0f / (BATCH * N_GT);
        const float inv_rad = 1.0f / (BATCH * N_RAD);
        float mean1     = r1[0] * inv_up;
        float mean_sqrt = r2[0] * inv_up;
        float mean2     = r3[0] * inv_gt;
        float conf_loss = r4[0] * inv_rad;
        float chamfer = 0.5f * mean1 + 2.0f * mean2;
        out[0] = 0.5f * chamfer + 0.5f * conf_loss + mean_sqrt;  // ALPHA = 0.5
    }
}

extern "C" void kernel_launch(void* const* d_in, const int* in_sizes, int n_in,
                              void* d_out, int out_size)
{
    (void)in_sizes; (void)n_in; (void)out_size;
    const float* pc_up   = (const float*)d_in[0];
    // d_in[1] = pc_seed (unused by the reference loss)
    const float* pc_conf = (const float*)d_in[2];
    const float* pc2     = (const float*)d_in[3];
    const float* pc3     = (const float*)d_in[4];

    // No init kernel: zero-initialized (or reduce-reset) g_min arrays act as
    // +inf under the sign-flipped key encoding.
    pairs_kernel<<<1152, NTHREADS>>>(pc_up, pc2, pc3);
    reduce_partial<<<NRED, NTHREADS>>>(pc_conf);
    reduce_final<<<1, 64>>>((float*)d_out);
}

// round 12
// speedup vs baseline: 1.1473x; 1.0055x over previous
#include <cuda_runtime.h>

// Problem constants (fixed by setup_inputs)
#define BATCH 4
#define N_UP  8192
#define N_GT  8192
#define N_RAD 1024
#define RCHUNK 256         // radar pass: b-points per block tile
#define NTHREADS 256
#define NRED 64            // partial-reduce blocks

#define CHUNK 256          // fused path: gt points per chunk
#define NCHUNK 8           // chunks per fused block (2048-gt quarter)
#define REDSTRIDE 255      // col-major reduce array stride (odd -> conflict-free)

// Running min of squared distance per point, stored as sign-flipped float bits:
//   key = __float_as_int(d) ^ 0x80000000   (d >= 0)
// Keys are negative ints, monotone increasing in d, so zero-initialized state
// (signed 0 > any key) acts as +infinity. reduce_partial resets slots to 0
// after consuming them, so the invariant holds for every graph replay.
__device__ int g_min1[BATCH * N_UP];   // up -> gt
__device__ int g_min2[BATCH * N_GT];   // gt -> up
__device__ int g_min3[BATCH * N_RAD];  // radar -> gt
__device__ float g_part[NRED * 4];     // per-block partials: d1, sqrt1, d2, conf

typedef unsigned long long ull;

__device__ __forceinline__ int enc_key(float d) {
    return __float_as_int(d) ^ 0x80000000;
}
__device__ __forceinline__ float dec_key(int k) {
    return __int_as_float(k ^ 0x80000000);
}

__device__ __forceinline__ ull fma2(ull a, ull b, ull c) {
    ull d;
    asm("fma.rn.f32x2 %0, %1, %2, %3;" : "=l"(d) : "l"(a), "l"(b), "l"(c));
    return d;
}
__device__ __forceinline__ ull add2(ull a, ull b) {
    ull d;
    asm("add.rn.f32x2 %0, %1, %2;" : "=l"(d) : "l"(a), "l"(b));
    return d;
}
__device__ __forceinline__ ull pack2(float lo, float hi) {
    ull d;
    asm("mov.b64 %0, {%1, %2};" : "=l"(d)
        : "r"(__float_as_uint(lo)), "r"(__float_as_uint(hi)));
    return d;
}
__device__ __forceinline__ float2 unpack2(ull v) {
    unsigned lo, hi;
    asm("mov.b64 {%0, %1}, %2;" : "=r"(lo), "=r"(hi) : "l"(v));
    return make_float2(__uint_as_float(lo), __uint_as_float(hi));
}

// ---------------- shared memory (union: fused chamfer vs radar path) --------
// red layout: col-major, addr = row * REDSTRIDE + col
//   main loop:  row = ta (0..15), col = gt-col (0..255)   max 15*255+255 = 4080
//   final:      row = tb (0..15), col = up-idx (0..127)
struct SmemFused {
    ull   sb[2][CHUNK * 4];          // 2x8KB: dup-packed b {x,x},{y,y},{z,z},{nb,nb}
    float red[2][16 * REDSTRIDE + 1];// 2x~16KB: col-major reduce arrays
};
struct SmemRadar {
    ulonglong2 tile[RCHUNK * 2];     // 8KB
};
union SmemAll { SmemFused f; SmemRadar r; };

// ---------------- radar pass (unfused, APT=4) -------------------------------
// min_j (a^2 + b^2 - 2 a.b) = a^2 - 2 * max_j (a.b - 0.5*b^2)
__device__ __forceinline__ void radar_pass(
    ulonglong2* tile,
    const float* __restrict__ apts,
    const float* __restrict__ bpts,
    int* __restrict__ gout,
    int a_start, int b_start)
{
    const int tid = threadIdx.x;

    for (int i = tid; i < RCHUNK; i += NTHREADS) {
        const float* p = bpts + 3 * (b_start + i);
        float x = p[0], y = p[1], z = p[2];
        float nb2 = -0.5f * (x * x + y * y + z * z);
        tile[2 * i]     = make_ulonglong2(pack2(x, x), pack2(y, y));
        tile[2 * i + 1] = make_ulonglong2(pack2(z, z), pack2(nb2, nb2));
    }
    __syncthreads();

    ull AX[2], AY[2], AZ[2];
    float a2[4], smax[4];
#pragma unroll
    for (int p = 0; p < 2; ++p) {
        int i0 = a_start + tid + (2 * p) * NTHREADS;
        int i1 = a_start + tid + (2 * p + 1) * NTHREADS;
        const float* q0 = apts + 3 * i0;
        const float* q1 = apts + 3 * i1;
        float x0 = q0[0], y0 = q0[1], z0 = q0[2];
        float x1 = q1[0], y1 = q1[1], z1 = q1[2];
        AX[p] = pack2(x0, x1); AY[p] = pack2(y0, y1); AZ[p] = pack2(z0, z1);
        a2[2 * p]     = x0 * x0 + y0 * y0 + z0 * z0;
        a2[2 * p + 1] = x1 * x1 + y1 * y1 + z1 * z1;
        smax[2 * p] = smax[2 * p + 1] = -3.0e38f;
    }

#pragma unroll 4
    for (int k = 0; k < RCHUNK; ++k) {
        ulonglong2 p0 = tile[2 * k];
        ulonglong2 p1 = tile[2 * k + 1];
#pragma unroll
        for (int p = 0; p < 2; ++p) {
            ull acc = fma2(AZ[p], p1.x, p1.y);
            acc     = fma2(AY[p], p0.y, acc);
            acc     = fma2(AX[p], p0.x, acc);
            float2 s = unpack2(acc);
            smax[2 * p]     = fmaxf(smax[2 * p], s.x);
            smax[2 * p + 1] = fmaxf(smax[2 * p + 1], s.y);
        }
    }

#pragma unroll
    for (int j = 0; j < 4; ++j) {
        int idx = a_start + tid + j * NTHREADS;
        float d = fmaxf(fmaf(-2.0f, smax[j], a2[j]), 0.0f);
        atomicMin(gout + idx, enc_key(d));
    }
}

// ---------------- b-tile loader ---------------------------------------------
__device__ __forceinline__ void load_b_point(ull* sb, const float* __restrict__ Bp,
                                             int chunk, int slot)
{
    const float* p = Bp + 3 * (chunk * CHUNK + slot);
    float x = p[0], y = p[1], z = p[2];
    float nb = -0.5f * (x * x + y * y + z * z);
    ull* d = &sb[slot * 4];
    d[0] = pack2(x, x); d[1] = pack2(y, y);
    d[2] = pack2(z, z); d[3] = pack2(nb, nb);
}

// ---------------- pairs kernel ----------------------------------------------
// All 1152 blocks do 262144 pair evaluations (equal duration):
// blocks [0,1024):     fused chamfer up<->gt. Block = (batch, ablk of 128 up,
//                      gt-quarter of 2048). 8 chunks of 256 gt; APT=8;
//                      double-buffered sb+red; ONE sync/chunk. After the sync,
//                      low 128 threads col-reduce 2 columns each while high
//                      128 threads prefetch 2 b-points of chunk+2 each.
// blocks [1024,1152):  radar -> gt, unfused, 256-gt chunks.
// Grid = 1152 = 1.95 waves at 4 blocks/SM (592 slots) -> ~97% slot util.
__global__ void __launch_bounds__(NTHREADS, 4)
pairs_kernel(const float* __restrict__ pc_up,
             const float* __restrict__ pc2,
             const float* __restrict__ pc3)
{
    __shared__ SmemAll sm;
    const int tid = threadIdx.x;
    const int bid = blockIdx.x;

    if (bid < 1024) {
        const int batch = bid >> 8;          // 256 blocks per batch
        const int r2    = bid & 255;
        const int ablk  = r2 >> 2;           // 0..63 (128 up-points each)
        const int bq    = r2 & 3;            // gt quarter (2048 each)
        const float* Ap = pc_up + (batch * N_UP + ablk * 128) * 3;
        const float* Bp = pc2   + (batch * N_GT + bq * 2048) * 3;
        const int ta = tid & 15;   // a-group (8 a-points each)
        const int tb = tid >> 4;   // b-group (16 b-points each)

        // Thread's 8 a-points as 4 packed pairs; symmetric score needs -a^2/2.
        ull AX[4], AY[4], AZ[4], NA[4];
        float rowmax[8];
#pragma unroll
        for (int p = 0; p < 4; ++p) {
            const float* q0 = Ap + 3 * (ta * 8 + 2 * p);
            float x0 = q0[0], y0 = q0[1], z0 = q0[2];
            float x1 = q0[3], y1 = q0[4], z1 = q0[5];
            AX[p] = pack2(x0, x1); AY[p] = pack2(y0, y1); AZ[p] = pack2(z0, z1);
            NA[p] = pack2(-0.5f * (x0 * x0 + y0 * y0 + z0 * z0),
                          -0.5f * (x1 * x1 + y1 * y1 + z1 * z1));
            rowmax[2 * p] = rowmax[2 * p + 1] = -3.0e38f;
        }

        // Preamble: load chunks 0 and 1 (each thread loads slot tid of both).
        load_b_point(sm.f.sb[0], Bp, 0, tid);
        load_b_point(sm.f.sb[1], Bp, 1, tid);
        __syncthreads();

        for (int chunk = 0; chunk < NCHUNK; ++chunk) {
            const int buf = chunk & 1;

#pragma unroll
            for (int j = 0; j < 16; ++j) {
                const ull* bb = &sm.f.sb[buf][(tb * 16 + j) * 4];
                ull bx = bb[0], by = bb[1], bz = bb[2], nb = bb[3];
                float t[4];
#pragma unroll
                for (int p = 0; p < 4; ++p) {
                    ull acc = fma2(AZ[p], bz, nb);
                    acc     = fma2(AY[p], by, acc);
                    acc     = fma2(AX[p], bx, acc);
                    ull s   = add2(acc, NA[p]);          // s = a.b - a^2/2 - b^2/2 = -d/2
                    float2 f = unpack2(s);
                    rowmax[2 * p]     = fmaxf(rowmax[2 * p],     f.x);
                    rowmax[2 * p + 1] = fmaxf(rowmax[2 * p + 1], f.y);
                    t[p] = fmaxf(f.x, f.y);
                }
                // column partial for this b-point (single-shot per chunk, tree)
                float cj = fmaxf(fmaxf(t[0], t[1]), fmaxf(t[2], t[3]));
                sm.f.red[buf][ta * REDSTRIDE + tb * 16 + j] = cj;
            }
            __syncthreads();   // ONLY sync this chunk: red[buf] complete;
                               // sb[buf] reads done (free for chunk+2 prefetch)

            if (tid < 128) {
                // col reduce + global atomic (low half, 2 columns each)
                const float* rbase = sm.f.red[buf];
#pragma unroll
                for (int h = 0; h < 2; ++h) {
                    int c = tid + h * 128;
                    float m = rbase[c];
#pragma unroll
                    for (int i = 1; i < 16; ++i) m = fmaxf(m, rbase[i * REDSTRIDE + c]);
                    float d = fmaxf(-2.0f * m, 0.0f);
                    atomicMin(g_min2 + batch * N_GT + bq * 2048 + chunk * CHUNK + c,
                              enc_key(d));
                }
            } else if (chunk + 2 < NCHUNK) {
                // prefetch chunk+2 into the buffer compute just vacated (2 pts)
                load_b_point(sm.f.sb[buf], Bp, chunk + 2, tid - 128);
                load_b_point(sm.f.sb[buf], Bp, chunk + 2, tid);  // slot tid-128+128
            }
            // no second sync: next compute reads sb[buf^1] and writes red[buf^1],
            // both untouched by this phase; ordering proven by per-chunk barrier.
        }

        // row (up->gt) reduce across the 16 tb-groups (col-major: row=tb, col=a)
        // red[buf of last chunk]'s readers finished before the final chunk's
        // barrier, which all threads have passed -> safe to overwrite red[0].
#pragma unroll
        for (int j = 0; j < 8; ++j)
            sm.f.red[0][tb * REDSTRIDE + ta * 8 + j] = rowmax[j];
        __syncthreads();
        if (tid < 128) {
            const float* rbase = sm.f.red[0];
            float m = rbase[tid];
#pragma unroll
            for (int i = 1; i < 16; ++i) m = fmaxf(m, rbase[i * REDSTRIDE + tid]);
            float d = fmaxf(-2.0f * m, 0.0f);
            atomicMin(g_min1 + batch * N_UP + ablk * 128 + tid, enc_key(d));
        }
    } else {
        // radar -> gt: 128 blocks = 4 batches x 32 chunks of 256 gt
        const int r = bid - 1024;
        const int batch = r >> 5;
        const int g = r & 31;
        radar_pass(sm.r.tile, pc3, pc2 + batch * N_GT * 3, g_min3,
                   batch * N_RAD, g * RCHUNK);
    }
}

// ---------------- stage-1 reduction: 64 blocks, fixed slices ----------------
// Each block consumes a fixed slice of each min-array (and resets it to 0),
// reduces in a fixed-order smem tree, writes 4 partials. Deterministic.
__global__ void __launch_bounds__(NTHREADS)
reduce_partial(const float* __restrict__ conf)
{
    const int tid = threadIdx.x;
    const int bid = blockIdx.x;
    float s_d1 = 0.f, s_sqrt1 = 0.f, s_d2 = 0.f, s_conf = 0.f;
    const int4 zero4 = make_int4(0, 0, 0, 0);

    // v1: 8192 int4 total -> 128 per block
    {
        int4* v1 = (int4*)g_min1 + bid * 128;
        if (tid < 128) {
            int4 v = v1[tid];
            float d0 = dec_key(v.x), d1 = dec_key(v.y);
            float d2 = dec_key(v.z), d3 = dec_key(v.w);
            s_d1 = (d0 + d1) + (d2 + d3);
            s_sqrt1 = (sqrtf(d0) + sqrtf(d1)) + (sqrtf(d2) + sqrtf(d3));
            v1[tid] = zero4;
        }
    }
    // v2: 8192 int4 total -> 128 per block
    {
        int4* v2 = (int4*)g_min2 + bid * 128;
        if (tid < 128) {
            int4 v = v2[tid];
            s_d2 = (dec_key(v.x) + dec_key(v.y)) + (dec_key(v.z) + dec_key(v.w));
            v2[tid] = zero4;
        }
    }
    // v3: 1024 int4 total -> 16 per block
    {
        int4*         v3 = (int4*)g_min3 + bid * 16;
        const float4* c4 = (const float4*)conf + bid * 16;
        if (tid < 16) {
            int4 v = v3[tid];
            float4 c = c4[tid];
            float e0 = c.x - expf(-sqrtf(dec_key(v.x)));
            float e1 = c.y - expf(-sqrtf(dec_key(v.y)));
            float e2 = c.z - expf(-sqrtf(dec_key(v.z)));
            float e3 = c.w - expf(-sqrtf(dec_key(v.w)));
            s_conf = (e0 * e0 + e1 * e1) + (e2 * e2 + e3 * e3);
            v3[tid] = zero4;
        }
    }

    __shared__ float r1[NTHREADS], r2[NTHREADS], r3[NTHREADS], r4[NTHREADS];
    r1[tid] = s_d1; r2[tid] = s_sqrt1; r3[tid] = s_d2; r4[tid] = s_conf;
    __syncthreads();
    for (int s = NTHREADS / 2; s > 0; s >>= 1) {
        if (tid < s) {
            r1[tid] += r1[tid + s];
            r2[tid] += r2[tid + s];
            r3[tid] += r3[tid + s];
            r4[tid] += r4[tid + s];
        }
        __syncthreads();
    }
    if (tid == 0) {
        g_part[bid * 4 + 0] = r1[0];
        g_part[bid * 4 + 1] = r2[0];
        g_part[bid * 4 + 2] = r3[0];
        g_part[bid * 4 + 3] = r4[0];
    }
}

// ---------------- stage-2: combine 64 partials (fixed-order tree) -----------
__global__ void __launch_bounds__(64)
reduce_final(float* __restrict__ out)
{
    const int tid = threadIdx.x;
    __shared__ float r1[64], r2[64], r3[64], r4[64];
    r1[tid] = g_part[tid * 4 + 0];
    r2[tid] = g_part[tid * 4 + 1];
    r3[tid] = g_part[tid * 4 + 2];
    r4[tid] = g_part[tid * 4 + 3];
    __syncthreads();
    for (int s = 32; s > 0; s >>= 1) {
        if (tid < s) {
            r1[tid] += r1[tid + s];
            r2[tid] += r2[tid + s];
            r3[tid] += r3[tid + s];
            r4[tid] += r4[tid + s];
        }
        __syncthreads();
    }
    if (tid == 0) {
        const float inv_up  = 1.0f / (BATCH * N_UP);
        const float inv_gt  = 1.0f / (BATCH * N_GT);
        const float inv_rad = 1.0f / (BATCH * N_RAD);
        float mean1     = r1[0] * inv_up;
        float mean_sqrt = r2[0] * inv_up;
        float mean2     = r3[0] * inv_gt;
        float conf_loss = r4[0] * inv_rad;
        float chamfer = 0.5f * mean1 + 2.0f * mean2;
        out[0] = 0.5f * chamfer + 0.5f * conf_loss + mean_sqrt;  // ALPHA = 0.5
    }
}

extern "C" void kernel_launch(void* const* d_in, const int* in_sizes, int n_in,
                              void* d_out, int out_size)
{
    (void)in_sizes; (void)n_in; (void)out_size;
    const float* pc_up   = (const float*)d_in[0];
    // d_in[1] = pc_seed (unused by the reference loss)
    const float* pc_conf = (const float*)d_in[2];
    const float* pc2     = (const float*)d_in[3];
    const float* pc3     = (const float*)d_in[4];

    // No init kernel: zero-initialized (or reduce-reset) g_min arrays act as
    // +inf under the sign-flipped key encoding.
    pairs_kernel<<<1152, NTHREADS>>>(pc_up, pc2, pc3);
    reduce_partial<<<NRED, NTHREADS>>>(pc_conf);
    reduce_final<<<1, 64>>>((float*)d_out);
}